// round 2
// baseline (speedup 1.0000x reference)
#include <cuda_runtime.h>
#include <cstdint>
#include <cstddef>

#define NQ   25200
#define NB   16
#define NCLS 80
#define PC   85
#define TOPK 1024
#define MAXDET 300
#define CONF_THF 0.6f
#define IOU_THF  0.45f
#define MAX_WHF  4096.0f
#define CAND_CAP 2048

// ---------------- scratch (device globals: no allocation allowed) ----------------
__device__ float    g_score[NB * NQ];
__device__ int      g_cls[NB * NQ];
__device__ int      g_selidx[NB * TOPK];
__device__ float    g_selscore[NB * TOPK];
__device__ int      g_selcls[NB * TOPK];
__device__ float    g_obox[NB * TOPK * 4];   // class-offset xyxy (for IoU)
__device__ float    g_area[NB * TOPK];
__device__ float    g_rawbox[NB * TOPK * 4]; // raw xyxy (for det output)
__device__ unsigned g_mask[NB * TOPK * 32];  // suppression bitmask rows

__device__ __forceinline__ unsigned f2ord(float f) {
    unsigned u = __float_as_uint(f);
    return (u & 0x80000000u) ? ~u : (u | 0x80000000u);
}

// ---------------- kernel 1: per-anchor score/cls (warp per anchor) ----------------
__global__ void k1_score(const float* __restrict__ pred) {
    int warp = (blockIdx.x * blockDim.x + threadIdx.x) >> 5;
    int lane = threadIdx.x & 31;
    if (warp >= NB * NQ) return;
    const float* row = pred + (size_t)warp * PC;
    float obj = __ldg(row + 4);
    float best = -1e30f;
    int   bidx = 0;
    #pragma unroll
    for (int c = lane; c < NCLS; c += 32) {
        float p = __fmul_rn(__ldg(row + 5 + c), obj);
        if (p > best) { best = p; bidx = c; }   // strict > keeps lowest c in-thread
    }
    #pragma unroll
    for (int off = 16; off; off >>= 1) {
        float ov = __shfl_down_sync(0xffffffffu, best, off);
        int   oi = __shfl_down_sync(0xffffffffu, bidx, off);
        if (ov > best || (ov == best && oi < bidx)) { best = ov; bidx = oi; }
    }
    if (lane == 0) {
        bool valid = (obj > CONF_THF) && (best > CONF_THF);
        g_score[warp] = valid ? best : -1.0f;
        g_cls[warp]   = bidx;
    }
}

// ---------------- kernel 2: per-image radix-select top-1024 + sort + gather ----------------
__global__ void __launch_bounds__(1024) k2_select(const float* __restrict__ pred) {
    int img = blockIdx.x;
    int tid = threadIdx.x;
    const float* sc = g_score + img * NQ;

    __shared__ unsigned s_hist[256];
    __shared__ unsigned s_selbin;
    __shared__ int s_k;
    __shared__ int s_cnt;
    __shared__ unsigned long long s_key[CAND_CAP];

    // 4-pass MSB radix select: find exact 32-bit key of the 1024th-largest ord
    unsigned prefix = 0;
    int k = TOPK;
    for (int p = 0; p < 4; ++p) {
        int shift = 24 - 8 * p;
        unsigned fmask = (p == 0) ? 0u : (0xFFFFFFFFu << (32 - 8 * p));
        if (tid < 256) s_hist[tid] = 0;
        __syncthreads();
        for (int i = tid; i < NQ; i += 1024) {
            unsigned o = f2ord(sc[i]);
            if (((o ^ prefix) & fmask) == 0)
                atomicAdd(&s_hist[(o >> shift) & 255], 1u);
        }
        __syncthreads();
        if (tid == 0) {
            int kk = k;
            int b = 255;
            for (; b >= 0; --b) {
                unsigned c = s_hist[b];
                if ((int)c >= kk) break;
                kk -= (int)c;
            }
            if (b < 0) b = 0;
            s_selbin = (unsigned)b;
            s_k = kk;
        }
        __syncthreads();
        prefix |= s_selbin << shift;
        k = s_k;
        __syncthreads();
    }
    unsigned T = prefix;

    // compact all candidates with ord >= T
    if (tid == 0) s_cnt = 0;
    __syncthreads();
    for (int i = tid; i < NQ; i += 1024) {
        unsigned o = f2ord(sc[i]);
        if (o >= T) {
            int pos = atomicAdd(&s_cnt, 1);
            if (pos < CAND_CAP)
                s_key[pos] = ((unsigned long long)(~o) << 32) | (unsigned)i;
        }
    }
    __syncthreads();
    int n = s_cnt; if (n > CAND_CAP) n = CAND_CAP;
    for (int i = n + tid; i < CAND_CAP; i += 1024) s_key[i] = ~0ull;
    __syncthreads();

    // bitonic sort ascending over (~ord, idx) -> top-1024 = score desc, idx asc (jax-stable)
    for (unsigned kk2 = 2; kk2 <= CAND_CAP; kk2 <<= 1) {
        for (unsigned jj = kk2 >> 1; jj > 0; jj >>= 1) {
            unsigned t = (unsigned)tid;
            unsigned e = ((t & ~(jj - 1)) << 1) | (t & (jj - 1));
            unsigned pi = e | jj;
            bool up = ((e & kk2) == 0);
            unsigned long long a = s_key[e], b2 = s_key[pi];
            bool sw = up ? (a > b2) : (a < b2);
            if (sw) { s_key[e] = b2; s_key[pi] = a; }
            __syncthreads();
        }
    }

    // gather boxes for my entry (tid in [0,1024))
    unsigned long long key = s_key[tid];
    int aidx; float scr; int cls;
    if ((key >> 32) == 0xFFFFFFFFull) {   // padding (fewer than 1024 candidates)
        aidx = 0; scr = -1.0f; cls = 0;
    } else {
        aidx = (int)(unsigned)(key & 0xFFFFFFFFull);
        scr  = sc[aidx];
        cls  = g_cls[img * NQ + aidx];
    }
    const float* row = pred + ((size_t)(img * NQ + aidx)) * PC;
    float cx = row[0], cy = row[1], w = row[2], h = row[3];
    float hw = __fmul_rn(w, 0.5f), hh = __fmul_rn(h, 0.5f);
    float x1 = __fsub_rn(cx, hw), y1 = __fsub_rn(cy, hh);
    float x2 = __fadd_rn(cx, hw), y2 = __fadd_rn(cy, hh);
    float off = __fmul_rn((float)cls, MAX_WHF);
    float ox1 = __fadd_rn(x1, off), oy1 = __fadd_rn(y1, off);
    float ox2 = __fadd_rn(x2, off), oy2 = __fadd_rn(y2, off);

    int gi = img * TOPK + tid;
    g_selidx[gi]   = aidx;
    g_selscore[gi] = scr;
    g_selcls[gi]   = cls;
    g_rawbox[gi*4+0] = x1; g_rawbox[gi*4+1] = y1; g_rawbox[gi*4+2] = x2; g_rawbox[gi*4+3] = y2;
    g_obox[gi*4+0] = ox1; g_obox[gi*4+1] = oy1; g_obox[gi*4+2] = ox2; g_obox[gi*4+3] = oy2;
    g_area[gi] = __fmul_rn(__fsub_rn(ox2, ox1), __fsub_rn(oy2, oy1));
}

// ---------------- kernel 3: IoU suppression bitmask (upper triangular) ----------------
__global__ void __launch_bounds__(256) k3_mask() {
    int img = blockIdx.y;
    __shared__ float s_x1[TOPK], s_y1[TOPK], s_x2[TOPK], s_y2[TOPK], s_ar[TOPK];
    int tid = threadIdx.x;
    for (int j = tid; j < TOPK; j += 256) {
        int gj = img * TOPK + j;
        s_x1[j] = g_obox[gj*4+0]; s_y1[j] = g_obox[gj*4+1];
        s_x2[j] = g_obox[gj*4+2]; s_y2[j] = g_obox[gj*4+3];
        s_ar[j] = g_area[gj];
    }
    __syncthreads();

    int t = blockIdx.x * 256 + tid;  // 0..4095 : 4 threads per row, 8 words each
    int i = t >> 2;
    int q = t & 3;
    float ax1 = s_x1[i], ay1 = s_y1[i], ax2 = s_x2[i], ay2 = s_y2[i], aar = s_ar[i];
    for (int w = q * 8; w < q * 8 + 8; ++w) {
        unsigned bits = 0;
        if (w * 32 + 31 > i) {
            #pragma unroll 4
            for (int b = 0; b < 32; ++b) {
                int j = w * 32 + b;
                if (j > i) {
                    float xx1 = fmaxf(ax1, s_x1[j]);
                    float yy1 = fmaxf(ay1, s_y1[j]);
                    float xx2 = fminf(ax2, s_x2[j]);
                    float yy2 = fminf(ay2, s_y2[j]);
                    float iw = fmaxf(__fsub_rn(xx2, xx1), 0.0f);
                    float ih = fmaxf(__fsub_rn(yy2, yy1), 0.0f);
                    float inter = __fmul_rn(iw, ih);
                    float denom = __fadd_rn(__fsub_rn(__fadd_rn(aar, s_ar[j]), inter), 1e-9f);
                    if (__fdiv_rn(inter, denom) > IOU_THF) bits |= 1u << b;
                }
            }
        }
        g_mask[(img * TOPK + i) * 32 + w] = bits;
    }
}

// ---------------- kernel 4: greedy resolve + write outputs ----------------
__global__ void __launch_bounds__(1024) k4_out(const float* __restrict__ logits,
                                               float* __restrict__ out) {
    extern __shared__ unsigned s_mask[];  // TOPK*32 words = 128 KB
    __shared__ int s_keep[MAXDET];
    __shared__ unsigned s_valid[32];
    __shared__ int s_nk;
    int img = blockIdx.x;
    int tid = threadIdx.x;

    for (int t = tid; t < TOPK * 32; t += 1024)
        s_mask[t] = g_mask[img * TOPK * 32 + t];
    {
        bool v = g_selscore[img * TOPK + tid] > CONF_THF;
        unsigned bal = __ballot_sync(0xffffffffu, v);
        if ((tid & 31) == 0) s_valid[tid >> 5] = bal;
    }
    __syncthreads();

    if (tid < 32) {
        unsigned remv = 0;
        int nk = 0;
        for (int i = 0; i < TOPK; ++i) {
            unsigned sw = __shfl_sync(0xffffffffu, remv, i >> 5);
            bool sup = (sw >> (i & 31)) & 1u;
            bool v   = (s_valid[i >> 5] >> (i & 31)) & 1u;
            if (v && !sup) {
                if (tid == 0) s_keep[nk] = i;
                nk++;
                remv |= s_mask[i * 32 + tid];
                if (nk == MAXDET) break;   // only first 300 kept are emitted
            }
        }
        if (tid == 0) s_nk = nk;
    }
    __syncthreads();
    int nk = s_nk;

    float* det = out;                                  // (16,300,6)
    float* val = out + NB * MAXDET * 6;                // (16,300)
    float* lg  = out + NB * MAXDET * 6 + NB * MAXDET;  // (16,300,80)

    for (int t = tid; t < MAXDET * 6; t += 1024) {
        int s = t / 6, c = t % 6;
        float vv = 0.0f;
        if (s < nk) {
            int i  = s_keep[s];
            int gi = img * TOPK + i;
            if (c < 4)       vv = g_rawbox[gi * 4 + c];
            else if (c == 4) vv = g_selscore[gi];
            else             vv = (float)g_selcls[gi];
        }
        det[(img * MAXDET + s) * 6 + c] = vv;
    }
    for (int s = tid; s < MAXDET; s += 1024)
        val[img * MAXDET + s] = (s < nk) ? 1.0f : 0.0f;
    for (int t = tid; t < MAXDET * NCLS; t += 1024) {
        int s = t / NCLS, c = t % NCLS;
        float vv = 0.0f;
        if (s < nk) {
            int i = s_keep[s];
            int aidx = g_selidx[img * TOPK + i];
            vv = logits[((size_t)(img * NQ + aidx)) * NCLS + c];
        }
        lg[(img * MAXDET + s) * NCLS + c] = vv;
    }
}

// ---------------- launch ----------------
extern "C" void kernel_launch(void* const* d_in, const int* in_sizes, int n_in,
                              void* d_out, int out_size) {
    const float* pred   = (const float*)d_in[0];
    const float* logits = (const float*)d_in[1];
    float* out = (float*)d_out;

    int total_threads = NB * NQ * 32;
    int blocks = (total_threads + 255) / 256;
    k1_score<<<blocks, 256>>>(pred);
    k2_select<<<NB, 1024>>>(pred);
    k3_mask<<<dim3(16, NB), 256>>>();
    cudaFuncSetAttribute(k4_out, cudaFuncAttributeMaxDynamicSharedMemorySize, TOPK * 32 * 4);
    k4_out<<<NB, 1024, TOPK * 32 * 4>>>(logits, out);
}